// round 12
// baseline (speedup 1.0000x reference)
#include <cuda_runtime.h>
#include <mma.h>

using namespace nvcuda;

// Problem constants
constexpr int Bn  = 4;
constexpr int Sn  = 2048;
constexpr int Dn  = 1024;
constexpr int Hn  = 16;
constexpr int DKn = 64;
constexpr int MROWS = Bn * Sn;   // 8192

// ---------------- scratch (device globals; no cudaMalloc allowed) ----------
__device__ float g_q[(size_t)Bn * Hn * Sn * DKn];   // [B,H,S,DK]
__device__ float g_k[(size_t)Bn * Hn * Sn * DKn];
__device__ float g_v[(size_t)Bn * Hn * Sn * DKn];
__device__ float g_x[(size_t)Bn * Sn * Dn];         // [B,S,D] merged heads
__device__ int   g_flags[(Sn / 64) * (Sn / 64)];    // mask tile all-ones flags

// ---------------- mask tile reduction --------------------------------------
__global__ __launch_bounds__(256)
void mask_flags_kernel(const int* __restrict__ mask, int* __restrict__ flags)
{
    int t  = blockIdx.x;
    int qt = t / (Sn / 64);
    int kt = t % (Sn / 64);
    int ok = 1;
    for (int i = threadIdx.x; i < 64 * 64; i += 256) {
        int r = i >> 6, c = i & 63;
        if (mask[(size_t)(qt * 64 + r) * Sn + kt * 64 + c] == 0) ok = 0;
    }
    ok = __syncthreads_and(ok);
    if (threadIdx.x == 0) flags[t] = ok;
}

// ---------------- TF32 GEMM: Y = A @ W^T + bias -----------------------------
// A [M,K] row-major, W [N,K] row-major (torch Linear weight layout).
// splitHeads=1: out indexed as [B,H,S,DK]; else plain [M,N] row-major.
constexpr int GBM = 128, GBN = 64, GBK = 32;
constexpr int ALD = 40, BLD = 40, CLD = 72;   // padded smem leading dims

__global__ __launch_bounds__(256)
void gemm_tf32_kernel(const float* __restrict__ A, const float* __restrict__ W,
                      const float* __restrict__ bias, float* __restrict__ out,
                      int K, int N, int splitHeads)
{
    __shared__ __align__(32) float smem[GBM * CLD];   // 9216 floats = 36 KB, reused for epilogue
    float* As = smem;                 // GBM*ALD = 5120 floats
    float* Bs = smem + GBM * ALD;     // GBN*BLD = 2560 floats

    const int tid  = threadIdx.x;
    const int warp = tid >> 5;
    const int wr   = warp >> 1;       // 0..3  (rows)
    const int wc   = warp & 1;        // 0..1  (cols)
    const int m0   = blockIdx.y * GBM;
    const int n0   = blockIdx.x * GBN;

    wmma::fragment<wmma::accumulator, 16, 16, 8, float> c[2][2];
#pragma unroll
    for (int mi = 0; mi < 2; mi++)
#pragma unroll
        for (int ni = 0; ni < 2; ni++)
            wmma::fill_fragment(c[mi][ni], 0.0f);

    for (int k0 = 0; k0 < K; k0 += GBK) {
        // stage A tile 128x32 (1024 float4, 4 per thread)
#pragma unroll
        for (int i = 0; i < 4; i++) {
            int e = i * 256 + tid;
            int r = e >> 3, c4 = e & 7;
            *(float4*)(As + r * ALD + c4 * 4) =
                *(const float4*)(A + (size_t)(m0 + r) * K + k0 + c4 * 4);
        }
        // stage W tile 64x32 (512 float4, 2 per thread)
#pragma unroll
        for (int i = 0; i < 2; i++) {
            int e = i * 256 + tid;
            int r = e >> 3, c4 = e & 7;
            *(float4*)(Bs + r * BLD + c4 * 4) =
                *(const float4*)(W + (size_t)(n0 + r) * K + k0 + c4 * 4);
        }
        __syncthreads();

#pragma unroll
        for (int ks = 0; ks < GBK; ks += 8) {
            wmma::fragment<wmma::matrix_a, 16, 16, 8, wmma::precision::tf32, wmma::row_major> a[2];
            wmma::fragment<wmma::matrix_b, 16, 16, 8, wmma::precision::tf32, wmma::col_major> b[2];
#pragma unroll
            for (int mi = 0; mi < 2; mi++) {
                wmma::load_matrix_sync(a[mi], As + (wr * 32 + mi * 16) * ALD + ks, ALD);
#pragma unroll
                for (int t = 0; t < a[mi].num_elements; t++)
                    a[mi].x[t] = wmma::__float_to_tf32(a[mi].x[t]);
            }
#pragma unroll
            for (int ni = 0; ni < 2; ni++) {
                // W tile viewed as col-major KxN: element (k,n) at Bs[n*BLD + k]
                wmma::load_matrix_sync(b[ni], Bs + (wc * 32 + ni * 16) * BLD + ks, BLD);
#pragma unroll
                for (int t = 0; t < b[ni].num_elements; t++)
                    b[ni].x[t] = wmma::__float_to_tf32(b[ni].x[t]);
            }
#pragma unroll
            for (int mi = 0; mi < 2; mi++)
#pragma unroll
                for (int ni = 0; ni < 2; ni++)
                    wmma::mma_sync(c[mi][ni], a[mi], b[ni], c[mi][ni]);
        }
        __syncthreads();
    }

    // epilogue: stage C tile in smem, add bias, write out
#pragma unroll
    for (int mi = 0; mi < 2; mi++)
#pragma unroll
        for (int ni = 0; ni < 2; ni++)
            wmma::store_matrix_sync(smem + (wr * 32 + mi * 16) * CLD + wc * 32 + ni * 16,
                                    c[mi][ni], CLD, wmma::mem_row_major);
    __syncthreads();

#pragma unroll
    for (int i = 0; i < (GBM * GBN) / 256; i++) {
        int e  = i * 256 + tid;
        int r  = e >> 6;           // /GBN
        int cc = e & 63;
        float v = smem[r * CLD + cc] + bias[n0 + cc];
        int m = m0 + r;
        if (splitHeads) {
            int bb = m >> 11;               // / S
            int ss = m & (Sn - 1);
            int hh = (n0 + cc) >> 6;        // / DK
            int dk = (n0 + cc) & 63;
            out[(((size_t)bb * Hn + hh) * Sn + ss) * DKn + dk] = v;
        } else {
            out[(size_t)m * N + n0 + cc] = v;
        }
    }
}

// ---------------- flash attention (TF32 wmma, smem softmax) -----------------
constexpr int QLD = 72;
constexpr int ATT_SMEM = (5 * 64 * QLD + 2 * 64) * 4;   // Qs,Ks,Vs,Ps,Os + m,l

__global__ __launch_bounds__(128)
void attn_kernel(const float* __restrict__ q, const float* __restrict__ k,
                 const float* __restrict__ v, const int* __restrict__ mask,
                 const int* __restrict__ tflags, float* __restrict__ xout)
{
    extern __shared__ __align__(32) float sm[];
    float* Qs    = sm;
    float* Ks    = Qs + 64 * QLD;
    float* Vs    = Ks + 64 * QLD;
    float* Ps    = Vs + 64 * QLD;
    float* Os    = Ps + 64 * QLD;
    float* m_arr = Os + 64 * QLD;
    float* l_arr = m_arr + 64;

    const int tid  = threadIdx.x;
    const int warp = tid >> 5;
    const int bh   = blockIdx.y;       // 0..63
    const int q0   = blockIdx.x * 64;

    // load Q block [64,64]
    const float* qb = q + ((size_t)bh * Sn + q0) * DKn;
#pragma unroll
    for (int i = 0; i < 8; i++) {
        int e = i * 128 + tid;
        int r = e >> 4, c4 = e & 15;
        *(float4*)(Qs + r * QLD + c4 * 4) = *(const float4*)(qb + r * DKn + c4 * 4);
    }
#pragma unroll
    for (int i = 0; i < 32; i++) {
        int e = i * 128 + tid;
        Os[(e >> 6) * QLD + (e & 63)] = 0.0f;
    }
    if (tid < 64) { m_arr[tid] = -1e30f; l_arr[tid] = 0.0f; }
    __syncthreads();

    // preload Q fragments (constant across key blocks)
    wmma::fragment<wmma::matrix_a, 16, 16, 8, wmma::precision::tf32, wmma::row_major> qa[8];
#pragma unroll
    for (int ks = 0; ks < 8; ks++) {
        wmma::load_matrix_sync(qa[ks], Qs + warp * 16 * QLD + ks * 8, QLD);
#pragma unroll
        for (int t = 0; t < qa[ks].num_elements; t++)
            qa[ks].x[t] = wmma::__float_to_tf32(qa[ks].x[t]);
    }

    const int row  = tid >> 1;   // warp w owns rows 16w..16w+15 (matches its wmma rows)
    const int half = tid & 1;

    for (int j0 = 0; j0 < Sn; j0 += 64) {
        // load K,V blocks [64,64]
        const float* kb = k + ((size_t)bh * Sn + j0) * DKn;
        const float* vb = v + ((size_t)bh * Sn + j0) * DKn;
#pragma unroll
        for (int i = 0; i < 8; i++) {
            int e = i * 128 + tid;
            int r = e >> 4, c4 = e & 15;
            *(float4*)(Ks + r * QLD + c4 * 4) = *(const float4*)(kb + r * DKn + c4 * 4);
            *(float4*)(Vs + r * QLD + c4 * 4) = *(const float4*)(vb + r * DKn + c4 * 4);
        }
        __syncthreads();

        // S = Q @ K^T  (warp computes its 16 rows x 64 cols)
#pragma unroll
        for (int nf = 0; nf < 4; nf++) {
            wmma::fragment<wmma::accumulator, 16, 16, 8, float> acc;
            wmma::fill_fragment(acc, 0.0f);
#pragma unroll
            for (int ks = 0; ks < 8; ks++) {
                wmma::fragment<wmma::matrix_b, 16, 16, 8, wmma::precision::tf32, wmma::col_major> bK;
                // K row-major [j][d] == col-major KxN (k=d, n=j), ld=QLD
                wmma::load_matrix_sync(bK, Ks + nf * 16 * QLD + ks * 8, QLD);
#pragma unroll
                for (int t = 0; t < bK.num_elements; t++)
                    bK.x[t] = wmma::__float_to_tf32(bK.x[t]);
                wmma::mma_sync(acc, qa[ks], bK, acc);
            }
            wmma::store_matrix_sync(Ps + warp * 16 * QLD + nf * 16, acc, QLD, wmma::mem_row_major);
        }
        __syncwarp();

        // online softmax: 2 threads per row, 32 cols each (warp-local rows)
        const int flag = tflags[(q0 >> 6) * (Sn / 64) + (j0 >> 6)];
        float* prow = Ps + row * QLD + half * 32;
        float sv[32];
        float mx = -1e30f;
        if (flag) {
#pragma unroll
            for (int c = 0; c < 32; c++) {
                float s = prow[c] * 0.125f;          // 1/sqrt(64)
                sv[c] = s;
                mx = fmaxf(mx, s);
            }
        } else {
            const int* mrow = mask + (size_t)(q0 + row) * Sn + j0 + half * 32;
#pragma unroll
            for (int c = 0; c < 32; c++) {
                float s = prow[c] * 0.125f;
                if (mrow[c] == 0) s = -1e9f;
                sv[c] = s;
                mx = fmaxf(mx, s);
            }
        }
        mx = fmaxf(mx, __shfl_xor_sync(0xffffffffu, mx, 1));
        float mprev = m_arr[row];
        float mnew  = fmaxf(mprev, mx);
        float alpha = __expf(mprev - mnew);
        float sum = 0.0f;
#pragma unroll
        for (int c = 0; c < 32; c++) {
            float p = __expf(sv[c] - mnew);
            prow[c] = p;
            sum += p;
        }
        sum += __shfl_xor_sync(0xffffffffu, sum, 1);
        if (half == 0) {
            m_arr[row] = mnew;
            l_arr[row] = l_arr[row] * alpha + sum;
        }
        // rescale running O
        float* orow = Os + row * QLD + half * 32;
#pragma unroll
        for (int c4 = 0; c4 < 8; c4++) {
            float4 t = *(float4*)(orow + c4 * 4);
            t.x *= alpha; t.y *= alpha; t.z *= alpha; t.w *= alpha;
            *(float4*)(orow + c4 * 4) = t;
        }
        __syncwarp();

        // O += P @ V  (warp-local rows; Vs shared but stable until next sync)
#pragma unroll
        for (int nf = 0; nf < 4; nf++) {
            wmma::fragment<wmma::accumulator, 16, 16, 8, float> acc;
            wmma::load_matrix_sync(acc, Os + warp * 16 * QLD + nf * 16, QLD, wmma::mem_row_major);
#pragma unroll
            for (int ks = 0; ks < 8; ks++) {
                wmma::fragment<wmma::matrix_a, 16, 16, 8, wmma::precision::tf32, wmma::row_major> aP;
                wmma::fragment<wmma::matrix_b, 16, 16, 8, wmma::precision::tf32, wmma::row_major> bV;
                wmma::load_matrix_sync(aP, Ps + warp * 16 * QLD + ks * 8, QLD);
                wmma::load_matrix_sync(bV, Vs + ks * 8 * QLD + nf * 16, QLD);
#pragma unroll
                for (int t = 0; t < aP.num_elements; t++) aP.x[t] = wmma::__float_to_tf32(aP.x[t]);
#pragma unroll
                for (int t = 0; t < bV.num_elements; t++) bV.x[t] = wmma::__float_to_tf32(bV.x[t]);
                wmma::mma_sync(acc, aP, bV, acc);
            }
            wmma::store_matrix_sync(Os + warp * 16 * QLD + nf * 16, acc, QLD, wmma::mem_row_major);
        }
        __syncthreads();   // protect Ks/Vs before next block's overwrite
    }

    // normalize and write merged-head output [B,S,H,DK]
    float linv = 1.0f / l_arr[row];
    int bb = bh >> 4, hh = bh & 15;
    float* ob = xout + (((size_t)bb * Sn + q0 + row) * Hn + hh) * DKn + half * 32;
    const float* orow = Os + row * QLD + half * 32;
#pragma unroll
    for (int c4 = 0; c4 < 8; c4++) {
        float4 t = *(const float4*)(orow + c4 * 4);
        t.x *= linv; t.y *= linv; t.z *= linv; t.w *= linv;
        *(float4*)(ob + c4 * 4) = t;
    }
}

// ---------------- launch -----------------------------------------------------
extern "C" void kernel_launch(void* const* d_in, const int* in_sizes, int n_in,
                              void* d_out, int out_size)
{
    (void)in_sizes; (void)n_in; (void)out_size;

    const float* query = (const float*)d_in[0];
    const float* key_  = (const float*)d_in[1];
    const float* value = (const float*)d_in[2];
    const int*   mask  = (const int*)d_in[3];
    const float* Wq = (const float*)d_in[4];
    const float* bq = (const float*)d_in[5];
    const float* Wk = (const float*)d_in[6];
    const float* bk = (const float*)d_in[7];
    const float* Wv = (const float*)d_in[8];
    const float* bv = (const float*)d_in[9];
    const float* Wo = (const float*)d_in[10];
    const float* bo = (const float*)d_in[11];
    float* out = (float*)d_out;

    float *qp, *kp, *vp, *xp; int* fp;
    cudaGetSymbolAddress((void**)&qp, g_q);
    cudaGetSymbolAddress((void**)&kp, g_k);
    cudaGetSymbolAddress((void**)&vp, g_v);
    cudaGetSymbolAddress((void**)&xp, g_x);
    cudaGetSymbolAddress((void**)&fp, g_flags);

    cudaFuncSetAttribute((void*)attn_kernel,
                         cudaFuncAttributeMaxDynamicSharedMemorySize, ATT_SMEM);

    // 1) mask tile flags
    mask_flags_kernel<<<(Sn / 64) * (Sn / 64), 256>>>(mask, fp);

    // 2) Q/K/V projections -> [B,H,S,DK]
    dim3 ggrid(Dn / GBN, MROWS / GBM);   // (16, 64)
    gemm_tf32_kernel<<<ggrid, 256>>>(query, Wq, bq, qp, Dn, Dn, 1);
    gemm_tf32_kernel<<<ggrid, 256>>>(key_,  Wk, bk, kp, Dn, Dn, 1);
    gemm_tf32_kernel<<<ggrid, 256>>>(value, Wv, bv, vp, Dn, Dn, 1);

    // 3) attention -> [B,S,D]
    attn_kernel<<<dim3(Sn / 64, Bn * Hn), 128, ATT_SMEM>>>(qp, kp, vp, mask, fp, xp);

    // 4) output projection -> d_out
    gemm_tf32_kernel<<<ggrid, 256>>>(xp, Wo, bo, out, Dn, Dn, 0);
}

// round 13
// speedup vs baseline: 1.2036x; 1.2036x over previous
#include <cuda_runtime.h>
#include <mma.h>

using namespace nvcuda;

// Problem constants
constexpr int Bn  = 4;
constexpr int Sn  = 2048;
constexpr int Dn  = 1024;
constexpr int Hn  = 16;
constexpr int DKn = 64;
constexpr int MROWS = Bn * Sn;   // 8192

// ---------------- scratch (device globals; no cudaMalloc allowed) ----------
__device__ float g_q[(size_t)Bn * Hn * Sn * DKn];   // [B,H,S,DK]
__device__ float g_k[(size_t)Bn * Hn * Sn * DKn];
__device__ float g_v[(size_t)Bn * Hn * Sn * DKn];
__device__ float g_x[(size_t)Bn * Sn * Dn];         // [B,S,H,DK] merged heads
__device__ int   g_flags[(Sn / 64) * (Sn / 64)];    // mask tile all-ones flags

__device__ __forceinline__ float4 cvt4(float4 v) {
    v.x = wmma::__float_to_tf32(v.x);
    v.y = wmma::__float_to_tf32(v.y);
    v.z = wmma::__float_to_tf32(v.z);
    v.w = wmma::__float_to_tf32(v.w);
    return v;
}

// ---------------- mask tile reduction --------------------------------------
__global__ __launch_bounds__(256)
void mask_flags_kernel(const int* __restrict__ mask, int* __restrict__ flags)
{
    int t  = blockIdx.x;
    int qt = t / (Sn / 64);
    int kt = t % (Sn / 64);
    int ok = 1;
    for (int i = threadIdx.x; i < 64 * 64; i += 256) {
        int r = i >> 6, c = i & 63;
        if (mask[(size_t)(qt * 64 + r) * Sn + kt * 64 + c] == 0) ok = 0;
    }
    ok = __syncthreads_and(ok);
    if (threadIdx.x == 0) flags[t] = ok;
}

// ---------------- TF32 GEMM: Y = A @ W^T + bias -----------------------------
// A [M,1024] row-major, W [1024,1024] row-major (torch Linear layout).
// 128x128x32 block tile, reg-staged double buffering, tf32 conversion at staging.
constexpr int GBM = 128, GBN = 128, GBK = 32;
constexpr int SLD = 36;                        // stage leading dim (floats)
constexpr int CLD = 132;                       // epilogue leading dim
constexpr int GEMM_SMEM_FLOATS = 2 * 2 * GBM * SLD;   // 2 stages x (A+B) = 18432
constexpr int GEMM_SMEM = GEMM_SMEM_FLOATS * 4;       // 73728 B (epilogue 128x132=16896 fits)

__global__ __launch_bounds__(256, 1)
void gemm_tf32_kernel(const float* __restrict__ A, const float* __restrict__ W,
                      const float* __restrict__ bias, float* __restrict__ out,
                      int splitHeads)
{
    extern __shared__ __align__(16) float sm[];
    const int tid  = threadIdx.x;
    const int warp = tid >> 5;
    const int wr   = warp >> 2;        // 0..1
    const int wc   = warp & 3;         // 0..3
    const int m0   = blockIdx.y * GBM;
    const int n0   = blockIdx.x * GBN;
    const int K    = Dn;

    wmma::fragment<wmma::accumulator, 16, 16, 8, float> c[4][2];
#pragma unroll
    for (int mi = 0; mi < 4; mi++)
#pragma unroll
        for (int ni = 0; ni < 2; ni++)
            wmma::fill_fragment(c[mi][ni], 0.0f);

    const float* Ab = A + (size_t)m0 * K;
    const float* Wb = W + (size_t)n0 * K;

    // prologue: stage slab 0 into buffer 0 (convert to tf32 at STS)
    {
        float* As = sm;
        float* Bs = sm + GBM * SLD;
#pragma unroll
        for (int i = 0; i < 4; i++) {
            int e = i * 256 + tid;
            int r = e >> 3, c4 = e & 7;
            *(float4*)(As + r * SLD + c4 * 4) = cvt4(*(const float4*)(Ab + (size_t)r * K + c4 * 4));
            *(float4*)(Bs + r * SLD + c4 * 4) = cvt4(*(const float4*)(Wb + (size_t)r * K + c4 * 4));
        }
    }
    __syncthreads();

    const int NK = K / GBK;   // 32
    for (int s = 0; s < NK; s++) {
        float4 ra[4], rb[4];
        if (s + 1 < NK) {
            int k0 = (s + 1) * GBK;
#pragma unroll
            for (int i = 0; i < 4; i++) {
                int e = i * 256 + tid;
                int r = e >> 3, c4 = e & 7;
                ra[i] = *(const float4*)(Ab + (size_t)r * K + k0 + c4 * 4);
                rb[i] = *(const float4*)(Wb + (size_t)r * K + k0 + c4 * 4);
            }
        }

        const float* As = sm + (s & 1) * (2 * GBM * SLD);
        const float* Bs = As + GBM * SLD;
#pragma unroll
        for (int ks = 0; ks < 4; ks++) {
            wmma::fragment<wmma::matrix_a, 16, 16, 8, wmma::precision::tf32, wmma::row_major> a[4];
            wmma::fragment<wmma::matrix_b, 16, 16, 8, wmma::precision::tf32, wmma::col_major> b[2];
#pragma unroll
            for (int mi = 0; mi < 4; mi++)
                wmma::load_matrix_sync(a[mi], As + (wr * 64 + mi * 16) * SLD + ks * 8, SLD);
#pragma unroll
            for (int ni = 0; ni < 2; ni++)
                wmma::load_matrix_sync(b[ni], Bs + (wc * 32 + ni * 16) * SLD + ks * 8, SLD);
#pragma unroll
            for (int mi = 0; mi < 4; mi++)
#pragma unroll
                for (int ni = 0; ni < 2; ni++)
                    wmma::mma_sync(c[mi][ni], a[mi], b[ni], c[mi][ni]);
        }

        if (s + 1 < NK) {
            float* Ad = sm + ((s + 1) & 1) * (2 * GBM * SLD);
            float* Bd = Ad + GBM * SLD;
#pragma unroll
            for (int i = 0; i < 4; i++) {
                int e = i * 256 + tid;
                int r = e >> 3, c4 = e & 7;
                *(float4*)(Ad + r * SLD + c4 * 4) = cvt4(ra[i]);
                *(float4*)(Bd + r * SLD + c4 * 4) = cvt4(rb[i]);
            }
        }
        __syncthreads();
    }

    // epilogue: stage C in smem (reuse), add bias, write out
#pragma unroll
    for (int mi = 0; mi < 4; mi++)
#pragma unroll
        for (int ni = 0; ni < 2; ni++)
            wmma::store_matrix_sync(sm + (wr * 64 + mi * 16) * CLD + wc * 32 + ni * 16,
                                    c[mi][ni], CLD, wmma::mem_row_major);
    __syncthreads();

#pragma unroll
    for (int i = 0; i < 16; i++) {
        int e  = i * 256 + tid;
        int r  = e >> 5;
        int c4 = e & 31;
        float4 v = *(float4*)(sm + r * CLD + c4 * 4);
        float4 b4 = *(const float4*)(bias + n0 + c4 * 4);
        v.x += b4.x; v.y += b4.y; v.z += b4.z; v.w += b4.w;
        int m = m0 + r, col = n0 + c4 * 4;
        if (splitHeads) {
            int bb = m >> 11, ss = m & (Sn - 1);
            int hh = col >> 6, dk = col & 63;
            *(float4*)(out + (((size_t)bb * Hn + hh) * Sn + ss) * DKn + dk) = v;
        } else {
            *(float4*)(out + (size_t)m * Dn + col) = v;
        }
    }
}

// ---------------- flash attention v2: register O accumulators ---------------
constexpr int QLD = 68;   // conflict-free for fragment loads ((4r+c)&31 distinct)
constexpr int AQF = 128 * QLD;
constexpr int AKF = 64 * QLD;
constexpr int ATT_FLOATS = AQF /*Q*/ + AKF /*K*/ + AKF /*V*/ + AQF /*P*/ + 3 * 128;
constexpr int ATT_SMEM = ATT_FLOATS * 4;   // 105984 B -> 2 blocks/SM

__global__ __launch_bounds__(256, 2)
void attn_kernel(const float* __restrict__ q, const float* __restrict__ k,
                 const float* __restrict__ v, const int* __restrict__ mask,
                 const int* __restrict__ tflags, float* __restrict__ xout)
{
    extern __shared__ __align__(16) float sm[];
    float* Qs      = sm;
    float* Ks      = Qs + AQF;
    float* Vs      = Ks + AKF;
    float* Ps      = Vs + AKF;
    float* m_arr   = Ps + AQF;
    float* l_arr   = m_arr + 128;
    float* alpha_s = l_arr + 128;

    const int tid  = threadIdx.x;
    const int warp = tid >> 5;
    const int lane = tid & 31;
    const int bh   = blockIdx.y;             // 0..63
    const int q0   = blockIdx.x * 128;
    const int w16  = warp * 16;

    // load Q [128,64] (tf32-converted at staging)
    const float* qb = q + ((size_t)bh * Sn + q0) * DKn;
#pragma unroll
    for (int i = 0; i < 8; i++) {
        int e = i * 256 + tid;
        int r = e >> 4, c4 = e & 15;
        *(float4*)(Qs + r * QLD + c4 * 4) = cvt4(*(const float4*)(qb + (size_t)r * DKn + c4 * 4));
    }
    // row-index patch (each element of the 16x16 patch = its local row)
#pragma unroll
    for (int i = 0; i < 8; i++) {
        int e = i * 32 + lane;
        int r = e >> 4, cc = e & 15;
        Ps[(w16 + r) * QLD + cc] = (float)r;
    }
    if (tid < 128) { m_arr[tid] = -1e30f; l_arr[tid] = 0.0f; }
    __syncthreads();

    // preload Q fragments (constant across key blocks)
    wmma::fragment<wmma::matrix_a, 16, 16, 8, wmma::precision::tf32, wmma::row_major> qa[8];
#pragma unroll
    for (int ks = 0; ks < 8; ks++)
        wmma::load_matrix_sync(qa[ks], Qs + w16 * QLD + ks * 8, QLD);

    // learn accumulator-fragment row mapping (layout-agnostic)
    wmma::fragment<wmma::accumulator, 16, 16, 8, float> rowf;
    wmma::load_matrix_sync(rowf, Ps + w16 * QLD, QLD, wmma::mem_row_major);
    int ridx[8];
#pragma unroll
    for (int t = 0; t < 8; t++) ridx[t] = w16 + (int)rowf.x[t];

    // persistent O accumulators (16 rows x 64 cols per warp)
    wmma::fragment<wmma::accumulator, 16, 16, 8, float> oacc[4];
#pragma unroll
    for (int nf = 0; nf < 4; nf++) wmma::fill_fragment(oacc[nf], 0.0f);

    const int row  = tid >> 1;   // 0..127 (warp w owns rows 16w..16w+15)
    const int half = tid & 1;

    for (int j0 = 0; j0 < Sn; j0 += 64) {
        // load K,V tiles [64,64] (tf32 at staging)
        const float* kb = k + ((size_t)bh * Sn + j0) * DKn;
        const float* vb = v + ((size_t)bh * Sn + j0) * DKn;
#pragma unroll
        for (int i = 0; i < 4; i++) {
            int e = i * 256 + tid;
            int r = e >> 4, c4 = e & 15;
            *(float4*)(Ks + r * QLD + c4 * 4) = cvt4(*(const float4*)(kb + (size_t)r * DKn + c4 * 4));
            *(float4*)(Vs + r * QLD + c4 * 4) = cvt4(*(const float4*)(vb + (size_t)r * DKn + c4 * 4));
        }
        __syncthreads();

        // S = Q @ K^T  (warp: 16 rows x 64 cols -> Ps)
#pragma unroll
        for (int nf = 0; nf < 4; nf++) {
            wmma::fragment<wmma::accumulator, 16, 16, 8, float> sacc;
            wmma::fill_fragment(sacc, 0.0f);
#pragma unroll
            for (int ks = 0; ks < 8; ks++) {
                wmma::fragment<wmma::matrix_b, 16, 16, 8, wmma::precision::tf32, wmma::col_major> bK;
                wmma::load_matrix_sync(bK, Ks + (nf * 16) * QLD + ks * 8, QLD);
                wmma::mma_sync(sacc, qa[ks], bK, sacc);
            }
            wmma::store_matrix_sync(Ps + w16 * QLD + nf * 16, sacc, QLD, wmma::mem_row_major);
        }
        __syncwarp();

        // online softmax: 2 lanes per row, 32 cols each (warp-local rows)
        const int flag = tflags[((q0 + row) >> 6) * (Sn / 64) + (j0 >> 6)];
        float* prow = Ps + row * QLD + half * 32;
        float mx = -1e30f;
        if (flag) {
#pragma unroll
            for (int c4 = 0; c4 < 8; c4++) {
                float4 t4 = *(float4*)(prow + c4 * 4);
                t4.x *= 0.125f; t4.y *= 0.125f; t4.z *= 0.125f; t4.w *= 0.125f;
                mx = fmaxf(mx, fmaxf(fmaxf(t4.x, t4.y), fmaxf(t4.z, t4.w)));
                *(float4*)(prow + c4 * 4) = t4;
            }
        } else {
            const int* mrow = mask + (size_t)(q0 + row) * Sn + j0 + half * 32;
#pragma unroll
            for (int c4 = 0; c4 < 8; c4++) {
                float4 t4 = *(float4*)(prow + c4 * 4);
                int4 m4 = *(const int4*)(mrow + c4 * 4);
                t4.x = m4.x ? t4.x * 0.125f : -1e9f;
                t4.y = m4.y ? t4.y * 0.125f : -1e9f;
                t4.z = m4.z ? t4.z * 0.125f : -1e9f;
                t4.w = m4.w ? t4.w * 0.125f : -1e9f;
                mx = fmaxf(mx, fmaxf(fmaxf(t4.x, t4.y), fmaxf(t4.z, t4.w)));
                *(float4*)(prow + c4 * 4) = t4;
            }
        }
        mx = fmaxf(mx, __shfl_xor_sync(0xffffffffu, mx, 1));
        float mprev = m_arr[row];
        float mnew  = fmaxf(mprev, mx);
        float alpha = __expf(mprev - mnew);
        float sum = 0.0f;
#pragma unroll
        for (int c4 = 0; c4 < 8; c4++) {
            float4 t4 = *(float4*)(prow + c4 * 4);
            t4.x = __expf(t4.x - mnew); t4.y = __expf(t4.y - mnew);
            t4.z = __expf(t4.z - mnew); t4.w = __expf(t4.w - mnew);
            sum += t4.x + t4.y + t4.z + t4.w;
            t4 = cvt4(t4);
            *(float4*)(prow + c4 * 4) = t4;
        }
        sum += __shfl_xor_sync(0xffffffffu, sum, 1);
        if (half == 0) {
            m_arr[row]   = mnew;
            l_arr[row]   = l_arr[row] * alpha + sum;
            alpha_s[row] = alpha;
        }
        __syncwarp();

        // rescale register O by per-row alpha (via learned row mapping)
#pragma unroll
        for (int nf = 0; nf < 4; nf++)
#pragma unroll
            for (int t = 0; t < 8; t++)
                oacc[nf].x[t] *= alpha_s[ridx[t]];

        // O += P @ V  (registers)
#pragma unroll
        for (int ks = 0; ks < 8; ks++) {
            wmma::fragment<wmma::matrix_a, 16, 16, 8, wmma::precision::tf32, wmma::row_major> aP;
            wmma::load_matrix_sync(aP, Ps + w16 * QLD + ks * 8, QLD);
#pragma unroll
            for (int nf = 0; nf < 4; nf++) {
                wmma::fragment<wmma::matrix_b, 16, 16, 8, wmma::precision::tf32, wmma::row_major> bV;
                wmma::load_matrix_sync(bV, Vs + (ks * 8) * QLD + nf * 16, QLD);
                wmma::mma_sync(oacc[nf], aP, bV, oacc[nf]);
            }
        }
        __syncthreads();   // protect Ks/Vs before next tile's overwrite
    }

    // normalize by 1/l and write out [B,S,H,DK]
    if (tid < 128) alpha_s[tid] = 1.0f / l_arr[tid];
    __syncthreads();
#pragma unroll
    for (int nf = 0; nf < 4; nf++) {
#pragma unroll
        for (int t = 0; t < 8; t++)
            oacc[nf].x[t] *= alpha_s[ridx[t]];
        wmma::store_matrix_sync(Ps + w16 * QLD + nf * 16, oacc[nf], QLD, wmma::mem_row_major);
    }
    __syncthreads();

    int bb = bh >> 4, hh = bh & 15;
#pragma unroll
    for (int i = 0; i < 8; i++) {
        int e = i * 256 + tid;
        int r = e >> 4, c4 = e & 15;
        float4 t4 = *(float4*)(Ps + r * QLD + c4 * 4);
        *(float4*)(xout + (((size_t)bb * Sn + q0 + r) * Hn + hh) * DKn + c4 * 4) = t4;
    }
}

// ---------------- launch -----------------------------------------------------
extern "C" void kernel_launch(void* const* d_in, const int* in_sizes, int n_in,
                              void* d_out, int out_size)
{
    (void)in_sizes; (void)n_in; (void)out_size;

    const float* query = (const float*)d_in[0];
    const float* key_  = (const float*)d_in[1];
    const float* value = (const float*)d_in[2];
    const int*   mask  = (const int*)d_in[3];
    const float* Wq = (const float*)d_in[4];
    const float* bq = (const float*)d_in[5];
    const float* Wk = (const float*)d_in[6];
    const float* bk = (const float*)d_in[7];
    const float* Wv = (const float*)d_in[8];
    const float* bv = (const float*)d_in[9];
    const float* Wo = (const float*)d_in[10];
    const float* bo = (const float*)d_in[11];
    float* out = (float*)d_out;

    float *qp, *kp, *vp, *xp; int* fp;
    cudaGetSymbolAddress((void**)&qp, g_q);
    cudaGetSymbolAddress((void**)&kp, g_k);
    cudaGetSymbolAddress((void**)&vp, g_v);
    cudaGetSymbolAddress((void**)&xp, g_x);
    cudaGetSymbolAddress((void**)&fp, g_flags);

    cudaFuncSetAttribute((void*)gemm_tf32_kernel,
                         cudaFuncAttributeMaxDynamicSharedMemorySize, GEMM_SMEM);
    cudaFuncSetAttribute((void*)attn_kernel,
                         cudaFuncAttributeMaxDynamicSharedMemorySize, ATT_SMEM);

    // 1) mask tile flags
    mask_flags_kernel<<<(Sn / 64) * (Sn / 64), 256>>>(mask, fp);

    // 2) Q/K/V projections -> [B,H,S,DK]
    dim3 ggrid(Dn / GBN, MROWS / GBM);   // (8, 64)
    gemm_tf32_kernel<<<ggrid, 256, GEMM_SMEM>>>(query, Wq, bq, qp, 1);
    gemm_tf32_kernel<<<ggrid, 256, GEMM_SMEM>>>(key_,  Wk, bk, kp, 1);
    gemm_tf32_kernel<<<ggrid, 256, GEMM_SMEM>>>(value, Wv, bv, vp, 1);

    // 3) attention -> [B,S,D]
    attn_kernel<<<dim3(Sn / 128, Bn * Hn), 256, ATT_SMEM>>>(qp, kp, vp, mask, fp, xp);

    // 4) output projection -> d_out
    gemm_tf32_kernel<<<ggrid, 256, GEMM_SMEM>>>(xp, Wo, bo, out, 0);
}

// round 14
// speedup vs baseline: 1.2053x; 1.0014x over previous
#include <cuda_runtime.h>
#include <mma.h>

using namespace nvcuda;

// Problem constants
constexpr int Bn  = 4;
constexpr int Sn  = 2048;
constexpr int Dn  = 1024;
constexpr int Hn  = 16;
constexpr int DKn = 64;
constexpr int MROWS = Bn * Sn;   // 8192

// ---------------- scratch (device globals; no cudaMalloc allowed) ----------
__device__ float g_q[(size_t)Bn * Hn * Sn * DKn];   // [B,H,S,DK]
__device__ float g_k[(size_t)Bn * Hn * Sn * DKn];
__device__ float g_v[(size_t)Bn * Hn * Sn * DKn];
__device__ float g_x[(size_t)Bn * Sn * Dn];         // [B,S,H,DK] merged heads
__device__ int   g_flags[(Sn / 64) * (Sn / 64)];    // mask tile all-ones flags

__device__ __forceinline__ float4 cvt4(float4 v) {
    v.x = wmma::__float_to_tf32(v.x);
    v.y = wmma::__float_to_tf32(v.y);
    v.z = wmma::__float_to_tf32(v.z);
    v.w = wmma::__float_to_tf32(v.w);
    return v;
}

// ---------------- mask tile reduction --------------------------------------
__global__ __launch_bounds__(256)
void mask_flags_kernel(const int* __restrict__ mask, int* __restrict__ flags)
{
    int t  = blockIdx.x;
    int qt = t / (Sn / 64);
    int kt = t % (Sn / 64);
    int ok = 1;
    for (int i = threadIdx.x; i < 64 * 64; i += 256) {
        int r = i >> 6, c = i & 63;
        if (mask[(size_t)(qt * 64 + r) * Sn + kt * 64 + c] == 0) ok = 0;
    }
    ok = __syncthreads_and(ok);
    if (threadIdx.x == 0) flags[t] = ok;
}

// ---------------- TF32 GEMM: Y = A @ W^T + bias -----------------------------
// A [M,1024] row-major, W [1024,1024] row-major (torch Linear layout).
// 128x128x32 block tile, reg-staged double buffering, tf32 conversion at staging.
constexpr int GBM = 128, GBN = 128, GBK = 32;
constexpr int SLD = 36;                        // stage leading dim (floats)
constexpr int CLD = 132;                       // epilogue leading dim
constexpr int GEMM_SMEM_FLOATS = 2 * 2 * GBM * SLD;   // 2 stages x (A+B) = 18432
constexpr int GEMM_SMEM = GEMM_SMEM_FLOATS * 4;       // 73728 B (epilogue 128x132=16896 fits)

__global__ __launch_bounds__(256, 1)
void gemm_tf32_kernel(const float* __restrict__ A, const float* __restrict__ W,
                      const float* __restrict__ bias, float* __restrict__ out,
                      int splitHeads)
{
    extern __shared__ __align__(16) float sm[];
    const int tid  = threadIdx.x;
    const int warp = tid >> 5;
    const int wr   = warp >> 2;        // 0..1
    const int wc   = warp & 3;         // 0..3
    const int m0   = blockIdx.y * GBM;
    const int n0   = blockIdx.x * GBN;
    const int K    = Dn;

    wmma::fragment<wmma::accumulator, 16, 16, 8, float> c[4][2];
#pragma unroll
    for (int mi = 0; mi < 4; mi++)
#pragma unroll
        for (int ni = 0; ni < 2; ni++)
            wmma::fill_fragment(c[mi][ni], 0.0f);

    const float* Ab = A + (size_t)m0 * K;
    const float* Wb = W + (size_t)n0 * K;

    // prologue: stage slab 0 into buffer 0 (convert to tf32 at STS)
    {
        float* As = sm;
        float* Bs = sm + GBM * SLD;
#pragma unroll
        for (int i = 0; i < 4; i++) {
            int e = i * 256 + tid;
            int r = e >> 3, c4 = e & 7;
            *(float4*)(As + r * SLD + c4 * 4) = cvt4(*(const float4*)(Ab + (size_t)r * K + c4 * 4));
            *(float4*)(Bs + r * SLD + c4 * 4) = cvt4(*(const float4*)(Wb + (size_t)r * K + c4 * 4));
        }
    }
    __syncthreads();

    const int NK = K / GBK;   // 32
    for (int s = 0; s < NK; s++) {
        float4 ra[4], rb[4];
        if (s + 1 < NK) {
            int k0 = (s + 1) * GBK;
#pragma unroll
            for (int i = 0; i < 4; i++) {
                int e = i * 256 + tid;
                int r = e >> 3, c4 = e & 7;
                ra[i] = *(const float4*)(Ab + (size_t)r * K + k0 + c4 * 4);
                rb[i] = *(const float4*)(Wb + (size_t)r * K + k0 + c4 * 4);
            }
        }

        const float* As = sm + (s & 1) * (2 * GBM * SLD);
        const float* Bs = As + GBM * SLD;
#pragma unroll
        for (int ks = 0; ks < 4; ks++) {
            wmma::fragment<wmma::matrix_a, 16, 16, 8, wmma::precision::tf32, wmma::row_major> a[4];
            wmma::fragment<wmma::matrix_b, 16, 16, 8, wmma::precision::tf32, wmma::col_major> b[2];
#pragma unroll
            for (int mi = 0; mi < 4; mi++)
                wmma::load_matrix_sync(a[mi], As + (wr * 64 + mi * 16) * SLD + ks * 8, SLD);
#pragma unroll
            for (int ni = 0; ni < 2; ni++)
                wmma::load_matrix_sync(b[ni], Bs + (wc * 32 + ni * 16) * SLD + ks * 8, SLD);
#pragma unroll
            for (int mi = 0; mi < 4; mi++)
#pragma unroll
                for (int ni = 0; ni < 2; ni++)
                    wmma::mma_sync(c[mi][ni], a[mi], b[ni], c[mi][ni]);
        }

        if (s + 1 < NK) {
            float* Ad = sm + ((s + 1) & 1) * (2 * GBM * SLD);
            float* Bd = Ad + GBM * SLD;
#pragma unroll
            for (int i = 0; i < 4; i++) {
                int e = i * 256 + tid;
                int r = e >> 3, c4 = e & 7;
                *(float4*)(Ad + r * SLD + c4 * 4) = cvt4(ra[i]);
                *(float4*)(Bd + r * SLD + c4 * 4) = cvt4(rb[i]);
            }
        }
        __syncthreads();
    }

    // epilogue: stage C in smem (reuse), add bias, write out
#pragma unroll
    for (int mi = 0; mi < 4; mi++)
#pragma unroll
        for (int ni = 0; ni < 2; ni++)
            wmma::store_matrix_sync(sm + (wr * 64 + mi * 16) * CLD + wc * 32 + ni * 16,
                                    c[mi][ni], CLD, wmma::mem_row_major);
    __syncthreads();

#pragma unroll
    for (int i = 0; i < 16; i++) {
        int e  = i * 256 + tid;
        int r  = e >> 5;
        int c4 = e & 31;
        float4 v = *(float4*)(sm + r * CLD + c4 * 4);
        float4 b4 = *(const float4*)(bias + n0 + c4 * 4);
        v.x += b4.x; v.y += b4.y; v.z += b4.z; v.w += b4.w;
        int m = m0 + r, col = n0 + c4 * 4;
        if (splitHeads) {
            int bb = m >> 11, ss = m & (Sn - 1);
            int hh = col >> 6, dk = col & 63;
            *(float4*)(out + (((size_t)bb * Hn + hh) * Sn + ss) * DKn + dk) = v;
        } else {
            *(float4*)(out + (size_t)m * Dn + col) = v;
        }
    }
}

// ---------------- flash attention v2: register O accumulators ---------------
constexpr int QLD = 68;   // conflict-free for fragment loads ((4r+c)&31 distinct)
constexpr int AQF = 128 * QLD;
constexpr int AKF = 64 * QLD;
constexpr int ATT_FLOATS = AQF /*Q*/ + AKF /*K*/ + AKF /*V*/ + AQF /*P*/ + 3 * 128;
constexpr int ATT_SMEM = ATT_FLOATS * 4;   // 105984 B -> 2 blocks/SM

__global__ __launch_bounds__(256, 2)
void attn_kernel(const float* __restrict__ q, const float* __restrict__ k,
                 const float* __restrict__ v, const int* __restrict__ mask,
                 const int* __restrict__ tflags, float* __restrict__ xout)
{
    extern __shared__ __align__(16) float sm[];
    float* Qs      = sm;
    float* Ks      = Qs + AQF;
    float* Vs      = Ks + AKF;
    float* Ps      = Vs + AKF;
    float* m_arr   = Ps + AQF;
    float* l_arr   = m_arr + 128;
    float* alpha_s = l_arr + 128;

    const int tid  = threadIdx.x;
    const int warp = tid >> 5;
    const int lane = tid & 31;
    const int bh   = blockIdx.y;             // 0..63
    const int q0   = blockIdx.x * 128;
    const int w16  = warp * 16;

    // load Q [128,64] (tf32-converted at staging)
    const float* qb = q + ((size_t)bh * Sn + q0) * DKn;
#pragma unroll
    for (int i = 0; i < 8; i++) {
        int e = i * 256 + tid;
        int r = e >> 4, c4 = e & 15;
        *(float4*)(Qs + r * QLD + c4 * 4) = cvt4(*(const float4*)(qb + (size_t)r * DKn + c4 * 4));
    }
    // row-index patch (each element of the 16x16 patch = its local row)
#pragma unroll
    for (int i = 0; i < 8; i++) {
        int e = i * 32 + lane;
        int r = e >> 4, cc = e & 15;
        Ps[(w16 + r) * QLD + cc] = (float)r;
    }
    if (tid < 128) { m_arr[tid] = -1e30f; l_arr[tid] = 0.0f; }
    __syncthreads();

    // preload Q fragments (constant across key blocks)
    wmma::fragment<wmma::matrix_a, 16, 16, 8, wmma::precision::tf32, wmma::row_major> qa[8];
#pragma unroll
    for (int ks = 0; ks < 8; ks++)
        wmma::load_matrix_sync(qa[ks], Qs + w16 * QLD + ks * 8, QLD);

    // learn accumulator-fragment row mapping (layout-agnostic)
    wmma::fragment<wmma::accumulator, 16, 16, 8, float> rowf;
    wmma::load_matrix_sync(rowf, Ps + w16 * QLD, QLD, wmma::mem_row_major);
    int ridx[8];
#pragma unroll
    for (int t = 0; t < 8; t++) ridx[t] = w16 + (int)rowf.x[t];

    // persistent O accumulators (16 rows x 64 cols per warp)
    wmma::fragment<wmma::accumulator, 16, 16, 8, float> oacc[4];
#pragma unroll
    for (int nf = 0; nf < 4; nf++) wmma::fill_fragment(oacc[nf], 0.0f);

    const int row  = tid >> 1;   // 0..127 (warp w owns rows 16w..16w+15)
    const int half = tid & 1;

    for (int j0 = 0; j0 < Sn; j0 += 64) {
        // load K,V tiles [64,64] (tf32 at staging)
        const float* kb = k + ((size_t)bh * Sn + j0) * DKn;
        const float* vb = v + ((size_t)bh * Sn + j0) * DKn;
#pragma unroll
        for (int i = 0; i < 4; i++) {
            int e = i * 256 + tid;
            int r = e >> 4, c4 = e & 15;
            *(float4*)(Ks + r * QLD + c4 * 4) = cvt4(*(const float4*)(kb + (size_t)r * DKn + c4 * 4));
            *(float4*)(Vs + r * QLD + c4 * 4) = cvt4(*(const float4*)(vb + (size_t)r * DKn + c4 * 4));
        }
        __syncthreads();

        // S = Q @ K^T  (warp: 16 rows x 64 cols -> Ps)
#pragma unroll
        for (int nf = 0; nf < 4; nf++) {
            wmma::fragment<wmma::accumulator, 16, 16, 8, float> sacc;
            wmma::fill_fragment(sacc, 0.0f);
#pragma unroll
            for (int ks = 0; ks < 8; ks++) {
                wmma::fragment<wmma::matrix_b, 16, 16, 8, wmma::precision::tf32, wmma::col_major> bK;
                wmma::load_matrix_sync(bK, Ks + (nf * 16) * QLD + ks * 8, QLD);
                wmma::mma_sync(sacc, qa[ks], bK, sacc);
            }
            wmma::store_matrix_sync(Ps + w16 * QLD + nf * 16, sacc, QLD, wmma::mem_row_major);
        }
        __syncwarp();

        // online softmax: 2 lanes per row, 32 cols each (warp-local rows)
        const int flag = tflags[((q0 + row) >> 6) * (Sn / 64) + (j0 >> 6)];
        float* prow = Ps + row * QLD + half * 32;
        float mx = -1e30f;
        if (flag) {
#pragma unroll
            for (int c4 = 0; c4 < 8; c4++) {
                float4 t4 = *(float4*)(prow + c4 * 4);
                t4.x *= 0.125f; t4.y *= 0.125f; t4.z *= 0.125f; t4.w *= 0.125f;
                mx = fmaxf(mx, fmaxf(fmaxf(t4.x, t4.y), fmaxf(t4.z, t4.w)));
                *(float4*)(prow + c4 * 4) = t4;
            }
        } else {
            const int* mrow = mask + (size_t)(q0 + row) * Sn + j0 + half * 32;
#pragma unroll
            for (int c4 = 0; c4 < 8; c4++) {
                float4 t4 = *(float4*)(prow + c4 * 4);
                int4 m4 = *(const int4*)(mrow + c4 * 4);
                t4.x = m4.x ? t4.x * 0.125f : -1e9f;
                t4.y = m4.y ? t4.y * 0.125f : -1e9f;
                t4.z = m4.z ? t4.z * 0.125f : -1e9f;
                t4.w = m4.w ? t4.w * 0.125f : -1e9f;
                mx = fmaxf(mx, fmaxf(fmaxf(t4.x, t4.y), fmaxf(t4.z, t4.w)));
                *(float4*)(prow + c4 * 4) = t4;
            }
        }
        mx = fmaxf(mx, __shfl_xor_sync(0xffffffffu, mx, 1));
        float mprev = m_arr[row];
        float mnew  = fmaxf(mprev, mx);
        float alpha = __expf(mprev - mnew);
        float sum = 0.0f;
#pragma unroll
        for (int c4 = 0; c4 < 8; c4++) {
            float4 t4 = *(float4*)(prow + c4 * 4);
            t4.x = __expf(t4.x - mnew); t4.y = __expf(t4.y - mnew);
            t4.z = __expf(t4.z - mnew); t4.w = __expf(t4.w - mnew);
            sum += t4.x + t4.y + t4.z + t4.w;
            t4 = cvt4(t4);
            *(float4*)(prow + c4 * 4) = t4;
        }
        sum += __shfl_xor_sync(0xffffffffu, sum, 1);
        if (half == 0) {
            m_arr[row]   = mnew;
            l_arr[row]   = l_arr[row] * alpha + sum;
            alpha_s[row] = alpha;
        }
        __syncwarp();

        // rescale register O by per-row alpha (via learned row mapping)
#pragma unroll
        for (int nf = 0; nf < 4; nf++)
#pragma unroll
            for (int t = 0; t < 8; t++)
                oacc[nf].x[t] *= alpha_s[ridx[t]];

        // O += P @ V  (registers)
#pragma unroll
        for (int ks = 0; ks < 8; ks++) {
            wmma::fragment<wmma::matrix_a, 16, 16, 8, wmma::precision::tf32, wmma::row_major> aP;
            wmma::load_matrix_sync(aP, Ps + w16 * QLD + ks * 8, QLD);
#pragma unroll
            for (int nf = 0; nf < 4; nf++) {
                wmma::fragment<wmma::matrix_b, 16, 16, 8, wmma::precision::tf32, wmma::row_major> bV;
                wmma::load_matrix_sync(bV, Vs + (ks * 8) * QLD + nf * 16, QLD);
                wmma::mma_sync(oacc[nf], aP, bV, oacc[nf]);
            }
        }
        __syncthreads();   // protect Ks/Vs before next tile's overwrite
    }

    // normalize by 1/l and write out [B,S,H,DK]
    if (tid < 128) alpha_s[tid] = 1.0f / l_arr[tid];
    __syncthreads();
#pragma unroll
    for (int nf = 0; nf < 4; nf++) {
#pragma unroll
        for (int t = 0; t < 8; t++)
            oacc[nf].x[t] *= alpha_s[ridx[t]];
        wmma::store_matrix_sync(Ps + w16 * QLD + nf * 16, oacc[nf], QLD, wmma::mem_row_major);
    }
    __syncthreads();

    int bb = bh >> 4, hh = bh & 15;
#pragma unroll
    for (int i = 0; i < 8; i++) {
        int e = i * 256 + tid;
        int r = e >> 4, c4 = e & 15;
        float4 t4 = *(float4*)(Ps + r * QLD + c4 * 4);
        *(float4*)(xout + (((size_t)bb * Sn + q0 + r) * Hn + hh) * DKn + c4 * 4) = t4;
    }
}

// ---------------- launch -----------------------------------------------------
extern "C" void kernel_launch(void* const* d_in, const int* in_sizes, int n_in,
                              void* d_out, int out_size)
{
    (void)in_sizes; (void)n_in; (void)out_size;

    const float* query = (const float*)d_in[0];
    const float* key_  = (const float*)d_in[1];
    const float* value = (const float*)d_in[2];
    const int*   mask  = (const int*)d_in[3];
    const float* Wq = (const float*)d_in[4];
    const float* bq = (const float*)d_in[5];
    const float* Wk = (const float*)d_in[6];
    const float* bk = (const float*)d_in[7];
    const float* Wv = (const float*)d_in[8];
    const float* bv = (const float*)d_in[9];
    const float* Wo = (const float*)d_in[10];
    const float* bo = (const float*)d_in[11];
    float* out = (float*)d_out;

    float *qp, *kp, *vp, *xp; int* fp;
    cudaGetSymbolAddress((void**)&qp, g_q);
    cudaGetSymbolAddress((void**)&kp, g_k);
    cudaGetSymbolAddress((void**)&vp, g_v);
    cudaGetSymbolAddress((void**)&xp, g_x);
    cudaGetSymbolAddress((void**)&fp, g_flags);

    cudaFuncSetAttribute((void*)gemm_tf32_kernel,
                         cudaFuncAttributeMaxDynamicSharedMemorySize, GEMM_SMEM);
    cudaFuncSetAttribute((void*)attn_kernel,
                         cudaFuncAttributeMaxDynamicSharedMemorySize, ATT_SMEM);

    // 1) mask tile flags
    mask_flags_kernel<<<(Sn / 64) * (Sn / 64), 256>>>(mask, fp);

    // 2) Q/K/V projections -> [B,H,S,DK]
    dim3 ggrid(Dn / GBN, MROWS / GBM);   // (8, 64)
    gemm_tf32_kernel<<<ggrid, 256, GEMM_SMEM>>>(query, Wq, bq, qp, 1);
    gemm_tf32_kernel<<<ggrid, 256, GEMM_SMEM>>>(key_,  Wk, bk, kp, 1);
    gemm_tf32_kernel<<<ggrid, 256, GEMM_SMEM>>>(value, Wv, bv, vp, 1);

    // 3) attention -> [B,S,D]
    attn_kernel<<<dim3(Sn / 128, Bn * Hn), 256, ATT_SMEM>>>(qp, kp, vp, mask, fp, xp);

    // 4) output projection -> d_out
    gemm_tf32_kernel<<<ggrid, 256, GEMM_SMEM>>>(xp, Wo, bo, out, 0);
}